// round 17
// baseline (speedup 1.0000x reference)
#include <cuda_runtime.h>
#include <cuda_fp16.h>
#include <cstdint>

// QCNN_58025008169535
// x: [32,128,128,3] f32, w: [4,4,3] f32 -> out: [32, 127*127, 4] f32
//
// fp16 tensor-core formulation, transposed orientation (patches on M side,
// W register-resident on the B side); v' on the A side via tile-swap + sign.
// R17: SINGLE kernel — every block redundantly builds U into its own shared
// memory (no inter-block dependency, no flag/spin, no global W). Pixel
// prefetch LDGs issue before the build so DRAM latency hides under it.

#define DIM 16
#define NQ 4

static constexpr int Bc = 32, Hc = 128, Wc = 128;
static constexpr int PHc = Hc - 1, PWc = Wc - 1;
static constexpr int Pc = PHc * PWc;          // 16129
static constexpr int TOTALc = Bc * Pc;        // 516128
static constexpr int WTOT = TOTALc / 32;      // 16129 warp-iterations
static constexpr int TITER = 2;
static constexpr int NWARP = 4;
static constexpr int NBLK = (WTOT + NWARP * TITER - 1) / (NWARP * TITER);  // 2017

typedef unsigned int uint;

__device__ __forceinline__ float2 cmul(float2 a, float2 b) {
    return make_float2(fmaf(a.x, b.x, -a.y * b.y), fmaf(a.x, b.y, a.y * b.x));
}
__device__ __forceinline__ float2 cadd(float2 a, float2 b) {
    return make_float2(a.x + b.x, a.y + b.y);
}
__device__ __forceinline__ uint h2u(float a, float b) {
    __half2 h = __float22half2_rn(make_float2(a, b));
    return *reinterpret_cast<uint*>(&h);
}

#define MMA_F16(C0, C1, C2, C3, A0, A1, A2, A3, B0, B1)                       \
    asm volatile(                                                             \
        "mma.sync.aligned.m16n8k16.row.col.f32.f16.f16.f32 "                  \
        "{%0,%1,%2,%3}, {%4,%5,%6,%7}, {%8,%9}, {%0,%1,%2,%3};"               \
        : "+f"(C0), "+f"(C1), "+f"(C2), "+f"(C3)                              \
        : "r"(A0), "r"(A1), "r"(A2), "r"(A3), "r"(B0), "r"(B1))

// ---------------------------------------------------------------------------
// Per-block U build (128 threads) into scratch; emits fp16 hi/lo W to
// sWhi/sWlo. Scratch layout: sg@0 (512B) | sM@512 (8192B) | sT@8704 (4096B);
// sU@512 (2KB, over dead sM).
// ---------------------------------------------------------------------------
__device__ void build_U_block(const float* __restrict__ w, char* scratch,
                              uint (*sWhi)[16], uint (*sWlo)[16], int tid) {
    float2 (*sg)[4]      = reinterpret_cast<float2(*)[4]>(scratch);
    float2 (*sM)[16][16] = reinterpret_cast<float2(*)[16][16]>(scratch + 512);
    float2 (*sT)[16][16] = reinterpret_cast<float2(*)[16][16]>(scratch + 8704);
    float2 (*sU)[16]     = reinterpret_cast<float2(*)[16]>(scratch + 512);

    if (tid < 16) {
        float wx = w[tid * 3 + 0];
        float wy = w[tid * 3 + 1];
        float wz = w[tid * 3 + 2];
        float cx, sx, cy, sy, cz, sz;
        sincosf(0.5f * wx, &sx, &cx);
        sincosf(0.5f * wy, &sy, &cy);
        sincosf(0.5f * wz, &sz, &cz);
        float2 m00 = make_float2(cy * cx,  sy * sx);
        float2 m01 = make_float2(-sy * cx, -cy * sx);
        float2 m10 = make_float2(sy * cx,  -cy * sx);
        float2 m11 = make_float2(cy * cx,  -sy * sx);
        float2 e0 = make_float2(cz, -sz);
        float2 e1 = make_float2(cz,  sz);
        sg[tid][0] = cmul(e0, m00);
        sg[tid][1] = cmul(e0, m01);
        sg[tid][2] = cmul(e1, m10);
        sg[tid][3] = cmul(e1, m11);
    }
    __syncthreads();

    // Layer matrices: 1024 elems, 8 per thread (CZ signs folded)
#pragma unroll
    for (int r = 0; r < 8; r++) {
        int e = tid + 128 * r;
        int h = e >> 8;
        int st = e & 255;
        int s = st >> 4, t = st & 15;
        float2 prod = make_float2(1.f, 0.f);
#pragma unroll
        for (int q = 0; q < NQ; q++) {
            int sb = (s >> (3 - q)) & 1;
            int tb = (t >> (3 - q)) & 1;
            prod = cmul(prod, sg[h * 4 + q][sb * 2 + tb]);
        }
        bool neg = (((s & 12) == 12) ^ ((s & 3) == 3)) ^ ((s & 6) == 6);
        if (neg) { prod.x = -prod.x; prod.y = -prod.y; }
        sM[h][s][t] = prod;
    }
    __syncthreads();

    // T1 = M2*M1, T2 = M4*M3: 256 elems, 2 per thread
#pragma unroll
    for (int r = 0; r < 2; r++) {
        int e = tid + 128 * r;
        int s = e >> 4, t = e & 15;
        float2 a1 = make_float2(0.f, 0.f);
        float2 a2 = make_float2(0.f, 0.f);
#pragma unroll
        for (int k = 0; k < DIM; k++) {
            a1 = cadd(a1, cmul(sM[1][s][k], sM[0][k][t]));
            a2 = cadd(a2, cmul(sM[3][s][k], sM[2][k][t]));
        }
        sT[0][s][t] = a1;
        sT[1][s][t] = a2;
    }
    __syncthreads();

    // U = T2*T1 (sM dead -> sU aliases it): 256 elems, 2 per thread
#pragma unroll
    for (int r = 0; r < 2; r++) {
        int e = tid + 128 * r;
        int s = e >> 4, t = e & 15;
        float2 u = make_float2(0.f, 0.f);
#pragma unroll
        for (int k = 0; k < DIM; k++)
            u = cadd(u, cmul(sT[1][s][k], sT[0][k][t]));
        sU[s][t] = u;
    }
    __syncthreads();

    // Emit W = [ReU | -ImU] as fp16 half2 hi + residual lo: 256 pairs, 2/thread
#pragma unroll
    for (int r = 0; r < 2; r++) {
        int e = tid + 128 * r;
        int s = e >> 4, p = e & 15;
        float v0, v1;
        if (p < 8) { v0 = sU[s][2 * p].x;       v1 = sU[s][2 * p + 1].x; }
        else       { v0 = -sU[s][2 * p - 16].y; v1 = -sU[s][2 * p - 15].y; }
        __half h0 = __float2half_rn(v0);
        __half h1 = __float2half_rn(v1);
        __half l0 = __float2half_rn(v0 - __half2float(h0));
        __half l1 = __float2half_rn(v1 - __half2float(h1));
        __half2 hp = __halves2half2(h0, h1);
        __half2 lp = __halves2half2(l0, l1);
        sWhi[s][p] = *reinterpret_cast<uint*>(&hp);
        sWlo[s][p] = *reinterpret_cast<uint*>(&lp);
    }
    __syncthreads();
}

// ---------------------------------------------------------------------------
__device__ __forceinline__ void load_px(const float* __restrict__ x, int idx,
                                        float2* pre) {
    int b  = idx / Pc;
    int p  = idx - b * Pc;
    int ph = p / PWc;
    int pw = p - ph * PWc;
    const float* base = x + (((b * Hc) + ph) * Wc + pw) * 3;
#pragma unroll
    for (int n = 0; n < 4; n++) {
        int dy = n >> 1, dx = n & 1;
        const float* px = base + (dy * Wc + dx) * 3;
        pre[n] = make_float2(__ldg(px + 1), __ldg(px + 2));
    }
}

__global__ void __launch_bounds__(128, 7)
k_qcnn(const float* __restrict__ x, const float* __restrict__ w,
       float* __restrict__ out) {
    // scratch (12800B) aliased by v_sm (10240B) after the build; sW persistent.
    __shared__ __align__(16) char scratch[12800];
    __shared__ uint sWhi[16][16], sWlo[16][16];   // 2 KB

    int tid  = threadIdx.x;
    int wrp  = tid >> 5;
    int lane = tid & 31;
    int g    = lane >> 2;
    int mm   = lane & 3;

    int WiBase = (blockIdx.x * NWARP + wrp) * TITER;
    bool active = (WiBase < WTOT);

    // Prefetch first iteration's pixels BEFORE the build (hides DRAM latency)
    float2 pre[4], nxt[4];
    if (active) load_px(x, WiBase * 32 + lane, pre);

    // ---- per-block redundant U build (no inter-block dependency) ----
    build_U_block(w, scratch, sWhi, sWlo, tid);

    uint (*v_sm)[32][20] = reinterpret_cast<uint(*)[32][20]>(scratch);

    // --- B fragments (W), persistent: [nt][kt][2 regs] from shared ---
    uint Bh[2][2][2], Bl[2][2][2];
#pragma unroll
    for (int nt = 0; nt < 2; nt++)
#pragma unroll
        for (int kt = 0; kt < 2; kt++) {
            Bh[nt][kt][0] = sWhi[nt * 8 + g][kt * 8 + mm];
            Bh[nt][kt][1] = sWhi[nt * 8 + g][kt * 8 + mm + 4];
            Bl[nt][kt][0] = sWlo[nt * 8 + g][kt * 8 + mm];
            Bl[nt][kt][1] = sWlo[nt * 8 + g][kt * 8 + mm + 4];
        }

    if (!active) return;

#pragma unroll 1
    for (int it = 0; it < TITER; it++) {
        int Wi = WiBase + it;
        if (Wi >= WTOT) break;

        // ---- encode patch Wi*32 + lane, stage psi as fp16 pairs ----
        {
            float  cth[NQ];
            float2 eph[NQ];
#pragma unroll
            for (int n = 0; n < NQ; n++) {
                float sb, cb, sp, cp;
                __sincosf(1.57079632679489662f * pre[n].x, &sb, &cb);
                __sincosf(3.14159265358979323f * pre[n].y, &sp, &cp);
                cth[n] = cb;
                eph[n] = make_float2(sb * cp, sb * sp);
            }
            float2 ab[4], cd[4];
            ab[0] = make_float2(cth[0] * cth[1], 0.f);
            ab[1] = make_float2(cth[0] * eph[1].x, cth[0] * eph[1].y);
            ab[2] = make_float2(eph[0].x * cth[1], eph[0].y * cth[1]);
            ab[3] = cmul(eph[0], eph[1]);
            cd[0] = make_float2(cth[2] * cth[3], 0.f);
            cd[1] = make_float2(cth[2] * eph[3].x, cth[2] * eph[3].y);
            cd[2] = make_float2(eph[2].x * cth[3], eph[2].y * cth[3]);
            cd[3] = cmul(eph[2], eph[3]);

            float2 psi[16];
#pragma unroll
            for (int i = 0; i < 4; i++)
#pragma unroll
                for (int j = 0; j < 4; j++)
                    psi[i * 4 + j] = cmul(ab[i], cd[j]);

            uint4* vrow = reinterpret_cast<uint4*>(&v_sm[wrp][lane][0]);
            vrow[0] = make_uint4(h2u(psi[0].x,  psi[1].x),  h2u(psi[2].x,  psi[3].x),
                                 h2u(psi[4].x,  psi[5].x),  h2u(psi[6].x,  psi[7].x));
            vrow[1] = make_uint4(h2u(psi[8].x,  psi[9].x),  h2u(psi[10].x, psi[11].x),
                                 h2u(psi[12].x, psi[13].x), h2u(psi[14].x, psi[15].x));
            vrow[2] = make_uint4(h2u(psi[0].y,  psi[1].y),  h2u(psi[2].y,  psi[3].y),
                                 h2u(psi[4].y,  psi[5].y),  h2u(psi[6].y,  psi[7].y));
            vrow[3] = make_uint4(h2u(psi[8].y,  psi[9].y),  h2u(psi[10].y, psi[11].y),
                                 h2u(psi[12].y, psi[13].y), h2u(psi[14].y, psi[15].y));
        }
        __syncwarp();

        // prefetch next iteration's pixels
        {
            int WiN = (Wi + 1 < WTOT) ? (Wi + 1) : Wi;
            load_px(x, WiN * 32 + lane, nxt);
        }

        // ---- 2 M-groups of 16 patches ----
#pragma unroll
        for (int mg = 0; mg < 2; mg++) {
            const uint* va0 = &v_sm[wrp][mg * 16 + g][0];
            const uint* va1 = &v_sm[wrp][mg * 16 + g + 8][0];
            uint A0a = va0[mm],     A0b = va1[mm];
            uint A0c = va0[mm + 4], A0d = va1[mm + 4];
            uint A1a = va0[8 + mm],     A1b = va1[8 + mm];
            uint A1c = va0[8 + mm + 4], A1d = va1[8 + mm + 4];
            uint N0a = A0a ^ 0x80008000u, N0b = A0b ^ 0x80008000u;
            uint N0c = A0c ^ 0x80008000u, N0d = A0d ^ 0x80008000u;

            float e0 = 0.f, e1 = 0.f, e2 = 0.f, e3 = 0.f;
            float f0 = 0.f, f1 = 0.f, f2 = 0.f, f3 = 0.f;
            float h0 = 0.f, h1 = 0.f, h2 = 0.f, h3 = 0.f;
            float i0 = 0.f, i1 = 0.f, i2 = 0.f, i3 = 0.f;

            MMA_F16(e0, e1, e2, e3, A0a, A0b, A0c, A0d, Bh[0][0][0], Bh[0][0][1]);
            MMA_F16(h0, h1, h2, h3, A1a, A1b, A1c, A1d, Bh[0][0][0], Bh[0][0][1]);
            MMA_F16(e0, e1, e2, e3, A1a, A1b, A1c, A1d, Bh[0][1][0], Bh[0][1][1]);
            MMA_F16(h0, h1, h2, h3, N0a, N0b, N0c, N0d, Bh[0][1][0], Bh[0][1][1]);
            MMA_F16(f0, f1, f2, f3, A0a, A0b, A0c, A0d, Bh[1][0][0], Bh[1][0][1]);
            MMA_F16(i0, i1, i2, i3, A1a, A1b, A1c, A1d, Bh[1][0][0], Bh[1][0][1]);
            MMA_F16(f0, f1, f2, f3, A1a, A1b, A1c, A1d, Bh[1][1][0], Bh[1][1][1]);
            MMA_F16(i0, i1, i2, i3, N0a, N0b, N0c, N0d, Bh[1][1][0], Bh[1][1][1]);
            MMA_F16(e0, e1, e2, e3, A0a, A0b, A0c, A0d, Bl[0][0][0], Bl[0][0][1]);
            MMA_F16(h0, h1, h2, h3, A1a, A1b, A1c, A1d, Bl[0][0][0], Bl[0][0][1]);
            MMA_F16(e0, e1, e2, e3, A1a, A1b, A1c, A1d, Bl[0][1][0], Bl[0][1][1]);
            MMA_F16(h0, h1, h2, h3, N0a, N0b, N0c, N0d, Bl[0][1][0], Bl[0][1][1]);
            MMA_F16(f0, f1, f2, f3, A0a, A0b, A0c, A0d, Bl[1][0][0], Bl[1][0][1]);
            MMA_F16(i0, i1, i2, i3, A1a, A1b, A1c, A1d, Bl[1][0][0], Bl[1][0][1]);
            MMA_F16(f0, f1, f2, f3, A1a, A1b, A1c, A1d, Bl[1][1][0], Bl[1][1][1]);
            MMA_F16(i0, i1, i2, i3, N0a, N0b, N0c, N0d, Bl[1][1][0], Bl[1][1][1]);

            float p00 = fmaf(e0, e0, h0 * h0);
            float p01 = fmaf(e1, e1, h1 * h1);
            float p10 = fmaf(f0, f0, i0 * i0);
            float p11 = fmaf(f1, f1, i1 * i1);
            float q00 = fmaf(e2, e2, h2 * h2);
            float q01 = fmaf(e3, e3, h3 * h3);
            float q10 = fmaf(f2, f2, i2 * i2);
            float q11 = fmaf(f3, f3, i3 * i3);

            float pt0 = p00 + p01, pt1 = p10 + p11;
            float S_a  = pt0 + pt1;
            float Z0_a = pt0 - pt1;
            float Z3_a = (p00 - p01) + (p10 - p11);
            float qt0 = q00 + q01, qt1 = q10 + q11;
            float S_b  = qt0 + qt1;
            float Z0_b = qt0 - qt1;
            float Z3_b = (q00 - q01) + (q10 - q11);

#pragma unroll
            for (int r = 0; r < 2; r++) {
                int m = 1 << r;
                float sg2 = (lane & m) ? -1.f : 1.f;
                float p;
                p = __shfl_xor_sync(0xffffffffu, S_a,  m); S_a  = fmaf(sg2, S_a,  p);
                p = __shfl_xor_sync(0xffffffffu, Z0_a, m); Z0_a = fmaf(sg2, Z0_a, p);
                p = __shfl_xor_sync(0xffffffffu, Z3_a, m); Z3_a = fmaf(sg2, Z3_a, p);
                p = __shfl_xor_sync(0xffffffffu, S_b,  m); S_b  = fmaf(sg2, S_b,  p);
                p = __shfl_xor_sync(0xffffffffu, Z0_b, m); Z0_b = fmaf(sg2, Z0_b, p);
                p = __shfl_xor_sync(0xffffffffu, Z3_b, m); Z3_b = fmaf(sg2, Z3_b, p);
            }

            int P0 = Wi * 32 + mg * 16 + g;
            int P1 = P0 + 8;
            if (mm == 0) {
                out[P0 * 4 + 0] = Z0_a;  out[P0 * 4 + 3] = Z3_a;
                out[P1 * 4 + 0] = Z0_b;  out[P1 * 4 + 3] = Z3_b;
            } else if (mm == 2) {
                out[P0 * 4 + 1] = S_a;   out[P1 * 4 + 1] = S_b;
            } else if (mm == 1) {
                out[P0 * 4 + 2] = S_a;   out[P1 * 4 + 2] = S_b;
            }
        }

        __syncwarp();
        pre[0] = nxt[0]; pre[1] = nxt[1]; pre[2] = nxt[2]; pre[3] = nxt[3];
    }
}

extern "C" void kernel_launch(void* const* d_in, const int* in_sizes, int n_in,
                              void* d_out, int out_size) {
    const float* x = (const float*)d_in[0];
    const float* w = (const float*)d_in[1];
    float* out = (float*)d_out;

    k_qcnn<<<NBLK, NWARP * 32>>>(x, w, out);
}